// round 2
// baseline (speedup 1.0000x reference)
#include <cuda_runtime.h>
#include <math.h>

#define NN 100000
#define EE 1600000
#define HH 128
#define GG 256
#define CC 5

// -------- device scratch (static, allocation-free) --------
__device__ __align__(16) float g_bufA[NN * HH];
__device__ __align__(16) float g_bufB[NN * HH];
__device__ __align__(16) float g_xa[NN * 4];
__device__ int   g_cnt[NN];
__device__ int   g_fill[NN];
__device__ int   g_rowptr[NN + 1];
__device__ int   g_col[EE];
__device__ float g_dinv[NN];
__device__ __align__(16) float g_pooled[GG * HH];
__device__ float g_gcnt[GG];
__device__ int   g_shift;   // 0: indices are int32, 1: indices are int64 (read low word)

__device__ __forceinline__ float* bufsel(int k) { return k ? g_bufB : g_bufA; }

// -------- dtype detection: sample odd 32-bit words of edge_index --------
// int64 little-endian with values < 2^32  -> odd words all zero.
// int32 -> odd words are random node ids (~0 with prob 1e-5 each).
__global__ void detect_k(const int* __restrict__ w) {
    __shared__ int sor[256];
    int t = threadIdx.x;
    int o = 0;
    #pragma unroll
    for (int k = 0; k < 16; k++) {
        int j = (t * 16 + k) * (EE / 4096);   // spread samples over [0, EE)
        o |= w[2 * j + 1];                    // safe: < 2*EE words either way
    }
    sor[t] = o;
    __syncthreads();
    for (int s = 128; s; s >>= 1) { if (t < s) sor[t] |= sor[t + s]; __syncthreads(); }
    if (t == 0) g_shift = (sor[0] == 0) ? 1 : 0;
}

// -------- zero scratch --------
__global__ void zero_k() {
    int i = blockIdx.x * blockDim.x + threadIdx.x;
    if (i < NN) { g_cnt[i] = 0; g_fill[i] = 0; }
    if (i < GG * HH) g_pooled[i] = 0.0f;
    if (i < GG) g_gcnt[i] = 0.0f;
}

// -------- degree count (dst, real edges only) --------
__global__ void count_k(const int* __restrict__ w) {
    int e = blockIdx.x * blockDim.x + threadIdx.x;
    if (e >= EE) return;
    int sh = g_shift;
    int dst = w[(EE + e) << sh];
    atomicAdd(&g_cnt[dst], 1);
}

// -------- exclusive scan of g_cnt -> g_rowptr (single block) --------
__global__ void scan_k() {
    __shared__ int ssum[1024];
    int t = threadIdx.x;
    const int CH = (NN + 1023) / 1024;  // 98
    int lo = t * CH;
    int hi = lo + CH; if (hi > NN) hi = NN;
    int s = 0;
    for (int i = lo; i < hi; i++) s += g_cnt[i];
    ssum[t] = s;
    __syncthreads();
    for (int off = 1; off < 1024; off <<= 1) {
        int v = (t >= off) ? ssum[t - off] : 0;
        __syncthreads();
        ssum[t] += v;
        __syncthreads();
    }
    int excl = (t == 0) ? 0 : ssum[t - 1];
    for (int i = lo; i < hi; i++) { g_rowptr[i] = excl; excl += g_cnt[i]; }
    if (t == 1023) g_rowptr[NN] = ssum[1023];
}

// -------- dinv = (deg+1)^-0.5 (self-loop included) --------
__global__ void dinv_k() {
    int i = blockIdx.x * blockDim.x + threadIdx.x;
    if (i >= NN) return;
    g_dinv[i] = rsqrtf((float)g_cnt[i] + 1.0f);
}

// -------- CSR fill --------
__global__ void fill_k(const int* __restrict__ w) {
    int e = blockIdx.x * blockDim.x + threadIdx.x;
    if (e >= EE) return;
    int sh = g_shift;
    int src = w[e << sh];
    int dst = w[(EE + e) << sh];
    int pos = g_rowptr[dst] + atomicAdd(&g_fill[dst], 1);
    g_col[pos] = src;
}

// -------- aggregate raw x (F=4): warp per node, lanes over edges --------
__global__ void aggx_k(const float* __restrict__ x) {
    int warp = (blockIdx.x * blockDim.x + threadIdx.x) >> 5;
    if (warp >= NN) return;
    int lane = threadIdx.x & 31;
    int s = g_rowptr[warp], e = g_rowptr[warp + 1];
    float4 acc = make_float4(0.f, 0.f, 0.f, 0.f);
    const float4* xv = (const float4*)x;
    for (int p = s + lane; p < e; p += 32) {
        int src = g_col[p];
        float w = g_dinv[src];
        float4 v = xv[src];
        acc.x += w * v.x; acc.y += w * v.y; acc.z += w * v.z; acc.w += w * v.w;
    }
    #pragma unroll
    for (int off = 16; off; off >>= 1) {
        acc.x += __shfl_down_sync(0xffffffffu, acc.x, off);
        acc.y += __shfl_down_sync(0xffffffffu, acc.y, off);
        acc.z += __shfl_down_sync(0xffffffffu, acc.z, off);
        acc.w += __shfl_down_sync(0xffffffffu, acc.w, off);
    }
    if (lane == 0) {
        float di = g_dinv[warp];
        float4 sv = xv[warp];
        float wi = di * di;
        float4 o;
        o.x = acc.x * di + sv.x * wi;
        o.y = acc.y * di + sv.y * wi;
        o.z = acc.z * di + sv.z * wi;
        o.w = acc.w * di + sv.w * wi;
        ((float4*)g_xa)[warp] = o;
    }
}

// -------- layer-1 GEMM: xa[N,4] @ W1[4,128] + b1, relu -> g_bufA --------
__global__ void gemm1_k(const float* __restrict__ W1, const float* __restrict__ b1) {
    int idx = blockIdx.x * blockDim.x + threadIdx.x;
    if (idx >= NN * HH) return;
    int node = idx >> 7, j = idx & 127;
    float4 a = ((const float4*)g_xa)[node];
    float acc = b1[j];
    acc += a.x * W1[j];
    acc += a.y * W1[128 + j];
    acc += a.z * W1[256 + j];
    acc += a.w * W1[384 + j];
    g_bufA[idx] = fmaxf(acc, 0.0f);
}

// -------- H=128 aggregation: warp per node, float4 per lane --------
__global__ void aggh_k(int inb, int outb) {
    int warp = (blockIdx.x * blockDim.x + threadIdx.x) >> 5;
    if (warp >= NN) return;
    int lane = threadIdx.x & 31;
    int s = g_rowptr[warp], e = g_rowptr[warp + 1];
    float4 acc = make_float4(0.f, 0.f, 0.f, 0.f);
    const float4* hv = (const float4*)bufsel(inb);
    for (int p = s; p < e; p++) {
        int src = g_col[p];
        float w = g_dinv[src];
        float4 v = hv[src * 32 + lane];
        acc.x += w * v.x; acc.y += w * v.y; acc.z += w * v.z; acc.w += w * v.w;
    }
    float di = g_dinv[warp];
    float4 sv = hv[warp * 32 + lane];
    float wi = di * di;
    float4 o;
    o.x = acc.x * di + sv.x * wi;
    o.y = acc.y * di + sv.y * wi;
    o.z = acc.z * di + sv.z * wi;
    o.w = acc.w * di + sv.w * wi;
    ((float4*)bufsel(outb))[warp * 32 + lane] = o;
}

// -------- dense GEMM: in[N,128] @ W[128,128] + b, relu -> out --------
// 64 nodes per block, 256 threads, thread = 8 nodes x 4 cols micro-tile.
__global__ __launch_bounds__(256, 2) void gemmh_k(
    int inb, const float* __restrict__ W,
    const float* __restrict__ b, int outb) {
    __shared__ float Ws[16 * 128];
    __shared__ float Is[64 * 128];
    int t = threadIdx.x;
    int nodeBase = blockIdx.x * 64;
    int validNodes = NN - nodeBase; if (validNodes > 64) validNodes = 64;

    const float* in = bufsel(inb);
    float* out = bufsel(outb);

    const float4* I4 = (const float4*)(in + (size_t)nodeBase * HH);
    float4* Is4 = (float4*)Is;
    for (int i = t; i < validNodes * 32; i += 256) Is4[i] = I4[i];

    int colg = t & 31;   // 32 groups of 4 cols
    int rowg = t >> 5;   // 8 groups of 8 nodes
    float acc[8][4] = {};
    const float4* W4 = (const float4*)W;
    float4* Ws4 = (float4*)Ws;

    for (int kc = 0; kc < 128; kc += 16) {
        __syncthreads();
        #pragma unroll
        for (int i = 0; i < 2; i++) Ws4[t + i * 256] = W4[kc * 32 + t + i * 256];
        __syncthreads();
        #pragma unroll
        for (int k = 0; k < 16; k++) {
            float4 wv = Ws4[k * 32 + colg];
            #pragma unroll
            for (int r = 0; r < 8; r++) {
                float a = Is[(rowg * 8 + r) * 128 + kc + k];
                acc[r][0] += a * wv.x;
                acc[r][1] += a * wv.y;
                acc[r][2] += a * wv.z;
                acc[r][3] += a * wv.w;
            }
        }
    }
    float4 bb = ((const float4*)b)[colg];
    #pragma unroll
    for (int r = 0; r < 8; r++) {
        int node = nodeBase + rowg * 8 + r;
        if (node < NN) {
            float4 o;
            o.x = fmaxf(acc[r][0] + bb.x, 0.0f);
            o.y = fmaxf(acc[r][1] + bb.y, 0.0f);
            o.z = fmaxf(acc[r][2] + bb.z, 0.0f);
            o.w = fmaxf(acc[r][3] + bb.w, 0.0f);
            ((float4*)(out + (size_t)node * HH))[colg] = o;
        }
    }
}

// -------- global mean pool accumulation: warp per node, reads g_bufA --------
__global__ void pool_k(const int* __restrict__ wbatch) {
    int warp = (blockIdx.x * blockDim.x + threadIdx.x) >> 5;
    if (warp >= NN) return;
    int lane = threadIdx.x & 31;
    int sh = g_shift;
    int g = wbatch[warp << sh];
    float4 v = ((const float4*)g_bufA)[warp * 32 + lane];
    float* base = &g_pooled[g * HH + lane * 4];
    atomicAdd(base + 0, v.x);
    atomicAdd(base + 1, v.y);
    atomicAdd(base + 2, v.z);
    atomicAdd(base + 3, v.w);
    if (lane == 0) atomicAdd(&g_gcnt[g], 1.0f);
}

// -------- classifier head: pooled/cnt @ Wl + bl, sigmoid --------
__global__ void final_k(const float* __restrict__ Wl, const float* __restrict__ bl,
                        float* __restrict__ out) {
    int idx = blockIdx.x * blockDim.x + threadIdx.x;
    if (idx >= GG * CC) return;
    int g = idx / CC, c = idx % CC;
    float inv = 1.0f / fmaxf(g_gcnt[g], 1.0f);
    float acc = bl[c];
    const float* pr = &g_pooled[g * HH];
    #pragma unroll 4
    for (int k = 0; k < HH; k++) acc += pr[k] * inv * Wl[k * CC + c];
    out[idx] = 1.0f / (1.0f + expf(-acc));
}

extern "C" void kernel_launch(void* const* d_in, const int* in_sizes, int n_in,
                              void* d_out, int out_size) {
    const float* x     = (const float*)d_in[0];
    const int*   eiw   = (const int*)d_in[1];    // edge_index as raw 32-bit words
    const int*   batw  = (const int*)d_in[2];    // batch as raw 32-bit words
    const float* W1 = (const float*)d_in[3];
    const float* b1 = (const float*)d_in[4];
    const float* W2 = (const float*)d_in[5];
    const float* b2 = (const float*)d_in[6];
    const float* W3 = (const float*)d_in[7];
    const float* b3 = (const float*)d_in[8];
    const float* W4 = (const float*)d_in[9];
    const float* b4 = (const float*)d_in[10];
    const float* Wl = (const float*)d_in[11];
    const float* bl = (const float*)d_in[12];
    float* out = (float*)d_out;

    // ---- dtype detect + CSR build ----
    detect_k<<<1, 256>>>(eiw);
    zero_k<<<(NN + 255) / 256, 256>>>();
    count_k<<<(EE + 255) / 256, 256>>>(eiw);
    scan_k<<<1, 1024>>>();
    dinv_k<<<(NN + 255) / 256, 256>>>();
    fill_k<<<(EE + 255) / 256, 256>>>(eiw);

    const int WARP_BLOCKS = (NN * 32 + 255) / 256;
    const int GEMM_BLOCKS = (NN + 63) / 64;

    // ---- layer 1: aggregate x (F=4), then GEMM with W1 -> bufA ----
    aggx_k<<<WARP_BLOCKS, 256>>>(x);
    gemm1_k<<<(NN * HH + 255) / 256, 256>>>(W1, b1);

    // ---- layers 2-4: agg(h) then h@W (ping-pong A<->B) ----
    aggh_k<<<WARP_BLOCKS, 256>>>(0, 1);
    gemmh_k<<<GEMM_BLOCKS, 256>>>(1, W2, b2, 0);

    aggh_k<<<WARP_BLOCKS, 256>>>(0, 1);
    gemmh_k<<<GEMM_BLOCKS, 256>>>(1, W3, b3, 0);

    aggh_k<<<WARP_BLOCKS, 256>>>(0, 1);
    gemmh_k<<<GEMM_BLOCKS, 256>>>(1, W4, b4, 0);

    // ---- global mean pool + head ----
    pool_k<<<WARP_BLOCKS, 256>>>(batw);
    final_k<<<(GG * CC + 255) / 256, 256>>>(Wl, bl, out);
}

// round 3
// speedup vs baseline: 1.2637x; 1.2637x over previous
#include <cuda_runtime.h>
#include <cuda_fp16.h>
#include <math.h>

#define NN 100000
#define EE 1600000
#define HH 128
#define GG 256
#define CC 5
#define SCAN_CHUNK 1024
#define NBLK ((NN + SCAN_CHUNK - 1) / SCAN_CHUNK)   // 98

// -------- device scratch (static, allocation-free) --------
__device__ __align__(16) __half g_hA[NN * HH];
__device__ __align__(16) __half g_hB[NN * HH];
__device__ __align__(16) float  g_xa[NN * 4];
__device__ int   g_cnt[NN];
__device__ int   g_fill[NN];
__device__ int   g_rowptr[NN + 1];
__device__ int   g_col[EE];
__device__ float g_dinv[NN];
__device__ int   g_part[NBLK];
__device__ __align__(16) float g_pooled[GG * HH];
__device__ float g_gcnt[GG];
__device__ int   g_shift;   // 0: int32 indices, 1: int64 (read low word)

__device__ __forceinline__ __half* hsel(int k) { return k ? g_hB : g_hA; }

// -------- packed f32x2 helpers (sm_103a) --------
__device__ __forceinline__ unsigned long long pack2(float x, float y) {
    unsigned long long r;
    asm("mov.b64 %0, {%1,%2};" : "=l"(r) : "f"(x), "f"(y));
    return r;
}
__device__ __forceinline__ unsigned long long fma2(unsigned long long a,
                                                   unsigned long long b,
                                                   unsigned long long c) {
    unsigned long long d;
    asm("fma.rn.f32x2 %0, %1, %2, %3;" : "=l"(d) : "l"(a), "l"(b), "l"(c));
    return d;
}
__device__ __forceinline__ float2 unpack2(unsigned long long v) {
    float2 r;
    asm("mov.b64 {%0,%1}, %2;" : "=f"(r.x), "=f"(r.y) : "l"(v));
    return r;
}

// -------- dtype detection: sample odd 32-bit words of edge_index --------
__global__ void detect_k(const int* __restrict__ w) {
    __shared__ int sor[256];
    int t = threadIdx.x;
    int o = 0;
    #pragma unroll
    for (int k = 0; k < 16; k++) {
        int j = (t * 16 + k) * (EE / 4096);
        o |= w[2 * j + 1];
    }
    sor[t] = o;
    __syncthreads();
    for (int s = 128; s; s >>= 1) { if (t < s) sor[t] |= sor[t + s]; __syncthreads(); }
    if (t == 0) g_shift = (sor[0] == 0) ? 1 : 0;
}

// -------- zero scratch --------
__global__ void zero_k() {
    int i = blockIdx.x * blockDim.x + threadIdx.x;
    if (i < NN) { g_cnt[i] = 0; g_fill[i] = 0; }
    if (i < GG * HH) g_pooled[i] = 0.0f;
    if (i < GG) g_gcnt[i] = 0.0f;
}

// -------- degree count (dst, real edges only) --------
__global__ void count_k(const int* __restrict__ w) {
    int e = blockIdx.x * blockDim.x + threadIdx.x;
    if (e >= EE) return;
    int sh = g_shift;
    int dst = w[(EE + e) << sh];
    atomicAdd(&g_cnt[dst], 1);
}

// -------- parallel scan, phase 1: per-block partial sums --------
__global__ void part_k() {
    __shared__ int red[256];
    int b = blockIdx.x, t = threadIdx.x;
    int base = b * SCAN_CHUNK;
    int v = 0;
    for (int i = t; i < SCAN_CHUNK; i += 256) {
        int idx = base + i;
        if (idx < NN) v += g_cnt[idx];
    }
    red[t] = v;
    __syncthreads();
    for (int s = 128; s; s >>= 1) { if (t < s) red[t] += red[t + s]; __syncthreads(); }
    if (t == 0) g_part[b] = red[0];
}

// -------- phase 2: exclusive scan of 98 partials (1 block) --------
__global__ void scanpart_k() {
    __shared__ int sp[128];
    int t = threadIdx.x;
    int v = (t < NBLK) ? g_part[t] : 0;
    sp[t] = v;
    __syncthreads();
    for (int off = 1; off < 128; off <<= 1) {
        int u = (t >= off) ? sp[t - off] : 0;
        __syncthreads();
        sp[t] += u;
        __syncthreads();
    }
    if (t < NBLK) g_part[t] = sp[t] - v;   // exclusive
    if (t == 127) g_rowptr[NN] = sp[127];  // total
}

// -------- phase 3: per-block scan + rowptr + dinv --------
__global__ void scan3_k() {
    __shared__ int sp[SCAN_CHUNK];
    int b = blockIdx.x, t = threadIdx.x;
    int idx = b * SCAN_CHUNK + t;
    int v = (idx < NN) ? g_cnt[idx] : 0;
    sp[t] = v;
    __syncthreads();
    for (int off = 1; off < SCAN_CHUNK; off <<= 1) {
        int u = (t >= off) ? sp[t - off] : 0;
        __syncthreads();
        sp[t] += u;
        __syncthreads();
    }
    if (idx < NN) {
        g_rowptr[idx] = g_part[b] + sp[t] - v;
        g_dinv[idx] = rsqrtf((float)v + 1.0f);
    }
}

// -------- CSR fill --------
__global__ void fill_k(const int* __restrict__ w) {
    int e = blockIdx.x * blockDim.x + threadIdx.x;
    if (e >= EE) return;
    int sh = g_shift;
    int src = w[e << sh];
    int dst = w[(EE + e) << sh];
    int pos = g_rowptr[dst] + atomicAdd(&g_fill[dst], 1);
    g_col[pos] = src;
}

// -------- aggregate raw x (F=4): warp per node --------
__global__ void aggx_k(const float* __restrict__ x) {
    int warp = (blockIdx.x * blockDim.x + threadIdx.x) >> 5;
    if (warp >= NN) return;
    int lane = threadIdx.x & 31;
    int s = g_rowptr[warp], e = g_rowptr[warp + 1];
    float4 acc = make_float4(0.f, 0.f, 0.f, 0.f);
    const float4* xv = (const float4*)x;
    for (int p = s + lane; p < e; p += 32) {
        int src = g_col[p];
        float w = g_dinv[src];
        float4 v = xv[src];
        acc.x += w * v.x; acc.y += w * v.y; acc.z += w * v.z; acc.w += w * v.w;
    }
    #pragma unroll
    for (int off = 16; off; off >>= 1) {
        acc.x += __shfl_down_sync(0xffffffffu, acc.x, off);
        acc.y += __shfl_down_sync(0xffffffffu, acc.y, off);
        acc.z += __shfl_down_sync(0xffffffffu, acc.z, off);
        acc.w += __shfl_down_sync(0xffffffffu, acc.w, off);
    }
    if (lane == 0) {
        float di = g_dinv[warp];
        float4 sv = xv[warp];
        float wi = di * di;
        float4 o;
        o.x = acc.x * di + sv.x * wi;
        o.y = acc.y * di + sv.y * wi;
        o.z = acc.z * di + sv.z * wi;
        o.w = acc.w * di + sv.w * wi;
        ((float4*)g_xa)[warp] = o;
    }
}

// -------- layer-1 GEMM: xa[N,4]@W1 + b1, relu, prescale by dinv -> g_hA fp16 --------
__global__ void gemm1_k(const float* __restrict__ W1, const float* __restrict__ b1) {
    int idx = blockIdx.x * blockDim.x + threadIdx.x;   // NN*64
    if (idx >= NN * 64) return;
    int node = idx >> 6, jc = idx & 63;
    int j = jc * 2;
    float4 a = ((const float4*)g_xa)[node];
    float acc0 = b1[j]     + a.x * W1[j]     + a.y * W1[128 + j]     + a.z * W1[256 + j]     + a.w * W1[384 + j];
    float acc1 = b1[j + 1] + a.x * W1[j + 1] + a.y * W1[128 + j + 1] + a.z * W1[256 + j + 1] + a.w * W1[384 + j + 1];
    float d = g_dinv[node];
    __half2 h = __floats2half2_rn(fmaxf(acc0, 0.f) * d, fmaxf(acc1, 0.f) * d);
    ((__half2*)g_hA)[node * 64 + jc] = h;
}

// -------- fused GCN layer: gather(fp16, prescaled) -> Is, GEMM(f32x2) -> fp16 out ----
// 64 nodes/block, 256 threads. Gather: warp per node (8 each). GEMM: 8x4 microtile.
__global__ __launch_bounds__(256, 3) void layer_k(
    int insel, const float* __restrict__ W, const float* __restrict__ b,
    int outsel, int prescale) {
    __shared__ float Is[64 * 128];
    __shared__ float Ws[16 * 128];
    int t = threadIdx.x, lane = t & 31, wrp = t >> 5;
    int nodeBase = blockIdx.x * 64;
    const uint2* h2 = (const uint2*)hsel(insel);

    // ---- gather phase: a_n = dinv_n * (sum_src h'_src + h'_n) ----
    #pragma unroll 1
    for (int r = 0; r < 8; r++) {
        int n = nodeBase + wrp * 8 + r;
        if (n < NN) {
            int s = g_rowptr[n], e = g_rowptr[n + 1];
            uint2 sv = h2[n * 32 + lane];
            float2 lo = __half22float2(*(const __half2*)&sv.x);
            float2 hi = __half22float2(*(const __half2*)&sv.y);
            float4 acc = make_float4(lo.x, lo.y, hi.x, hi.y);
            for (int p = s; p < e; p++) {
                int src = __ldg(&g_col[p]);
                uint2 v = h2[src * 32 + lane];
                float2 l2 = __half22float2(*(const __half2*)&v.x);
                float2 h2f = __half22float2(*(const __half2*)&v.y);
                acc.x += l2.x; acc.y += l2.y; acc.z += h2f.x; acc.w += h2f.y;
            }
            float d = g_dinv[n];
            acc.x *= d; acc.y *= d; acc.z *= d; acc.w *= d;
            ((float4*)Is)[(wrp * 8 + r) * 32 + lane] = acc;
        }
    }

    // ---- GEMM phase: Is[64,128] @ W[128,128] ----
    int colg = t & 31;   // 32 groups x 4 cols
    int rowg = t >> 5;   // 8 groups x 8 rows
    unsigned long long acc01[8], acc23[8];
    unsigned long long z = pack2(0.f, 0.f);
    #pragma unroll
    for (int r = 0; r < 8; r++) { acc01[r] = z; acc23[r] = z; }

    const float2* Ws2 = (const float2*)Ws;
    for (int kc = 0; kc < 128; kc += 16) {
        __syncthreads();
        #pragma unroll
        for (int i = 0; i < 2; i++)
            ((float4*)Ws)[t + i * 256] = ((const float4*)W)[kc * 32 + t + i * 256];
        __syncthreads();
        #pragma unroll
        for (int k = 0; k < 16; k++) {
            unsigned long long w01 = *(const unsigned long long*)&Ws2[k * 64 + colg * 2];
            unsigned long long w23 = *(const unsigned long long*)&Ws2[k * 64 + colg * 2 + 1];
            #pragma unroll
            for (int r = 0; r < 8; r++) {
                float a = Is[(rowg * 8 + r) * 128 + kc + k];
                unsigned long long aa = pack2(a, a);
                acc01[r] = fma2(aa, w01, acc01[r]);
                acc23[r] = fma2(aa, w23, acc23[r]);
            }
        }
    }

    __half* hout = hsel(outsel);
    float2 bb01 = ((const float2*)b)[colg * 2];
    float2 bb23 = ((const float2*)b)[colg * 2 + 1];
    #pragma unroll
    for (int r = 0; r < 8; r++) {
        int node = nodeBase + rowg * 8 + r;
        if (node < NN) {
            float d = prescale ? g_dinv[node] : 1.0f;
            float2 v01 = unpack2(acc01[r]);
            float2 v23 = unpack2(acc23[r]);
            float o0 = fmaxf(v01.x + bb01.x, 0.f) * d;
            float o1 = fmaxf(v01.y + bb01.y, 0.f) * d;
            float o2 = fmaxf(v23.x + bb23.x, 0.f) * d;
            float o3 = fmaxf(v23.y + bb23.y, 0.f) * d;
            uint2 st;
            __half2 p0 = __floats2half2_rn(o0, o1);
            __half2 p1 = __floats2half2_rn(o2, o3);
            st.x = *(unsigned int*)&p0;
            st.y = *(unsigned int*)&p1;
            ((uint2*)hout)[node * 32 + colg] = st;
        }
    }
}

// -------- global mean pool: reads fp16 layer-4 output --------
__global__ void pool_k(const int* __restrict__ wbatch, int insel) {
    int warp = (blockIdx.x * blockDim.x + threadIdx.x) >> 5;
    if (warp >= NN) return;
    int lane = threadIdx.x & 31;
    int sh = g_shift;
    int g = wbatch[warp << sh];
    uint2 v = ((const uint2*)hsel(insel))[warp * 32 + lane];
    float2 lo = __half22float2(*(const __half2*)&v.x);
    float2 hi = __half22float2(*(const __half2*)&v.y);
    float* base = &g_pooled[g * HH + lane * 4];
    atomicAdd(base + 0, lo.x);
    atomicAdd(base + 1, lo.y);
    atomicAdd(base + 2, hi.x);
    atomicAdd(base + 3, hi.y);
    if (lane == 0) atomicAdd(&g_gcnt[g], 1.0f);
}

// -------- classifier head --------
__global__ void final_k(const float* __restrict__ Wl, const float* __restrict__ bl,
                        float* __restrict__ out) {
    int idx = blockIdx.x * blockDim.x + threadIdx.x;
    if (idx >= GG * CC) return;
    int g = idx / CC, c = idx % CC;
    float inv = 1.0f / fmaxf(g_gcnt[g], 1.0f);
    float acc = bl[c];
    const float* pr = &g_pooled[g * HH];
    #pragma unroll 4
    for (int k = 0; k < HH; k++) acc += pr[k] * inv * Wl[k * CC + c];
    out[idx] = 1.0f / (1.0f + expf(-acc));
}

extern "C" void kernel_launch(void* const* d_in, const int* in_sizes, int n_in,
                              void* d_out, int out_size) {
    const float* x    = (const float*)d_in[0];
    const int*   eiw  = (const int*)d_in[1];
    const int*   batw = (const int*)d_in[2];
    const float* W1 = (const float*)d_in[3];
    const float* b1 = (const float*)d_in[4];
    const float* W2 = (const float*)d_in[5];
    const float* b2 = (const float*)d_in[6];
    const float* W3 = (const float*)d_in[7];
    const float* b3 = (const float*)d_in[8];
    const float* W4 = (const float*)d_in[9];
    const float* b4 = (const float*)d_in[10];
    const float* Wl = (const float*)d_in[11];
    const float* bl = (const float*)d_in[12];
    float* out = (float*)d_out;

    // ---- dtype detect + CSR build ----
    detect_k<<<1, 256>>>(eiw);
    zero_k<<<(NN + 255) / 256, 256>>>();
    count_k<<<(EE + 255) / 256, 256>>>(eiw);
    part_k<<<NBLK, 256>>>();
    scanpart_k<<<1, 128>>>();
    scan3_k<<<NBLK, SCAN_CHUNK>>>();
    fill_k<<<(EE + 255) / 256, 256>>>(eiw);

    const int WARP_BLOCKS = (NN * 32 + 255) / 256;
    const int LAYER_BLOCKS = (NN + 63) / 64;

    // ---- layer 1: aggregate x (F=4), GEMM W1 -> g_hA (prescaled fp16) ----
    aggx_k<<<WARP_BLOCKS, 256>>>(x);
    gemm1_k<<<(NN * 64 + 255) / 256, 256>>>(W1, b1);

    // ---- layers 2-4: fused gather + GEMM (ping-pong A<->B) ----
    layer_k<<<LAYER_BLOCKS, 256>>>(0, W2, b2, 1, 1);
    layer_k<<<LAYER_BLOCKS, 256>>>(1, W3, b3, 0, 1);
    layer_k<<<LAYER_BLOCKS, 256>>>(0, W4, b4, 1, 0);   // last layer: no prescale

    // ---- global mean pool + head ----
    pool_k<<<WARP_BLOCKS, 256>>>(batw, 1);
    final_k<<<(GG * CC + 255) / 256, 256>>>(Wl, bl, out);
}

// round 4
// speedup vs baseline: 2.3020x; 1.8217x over previous
#include <cuda_runtime.h>
#include <cuda_fp16.h>
#include <math.h>

#define NN 100000
#define EE 1600000
#define HH 128
#define GG 256
#define CC 5
#define SCAN_CHUNK 1024
#define NBLK ((NN + SCAN_CHUNK - 1) / SCAN_CHUNK)   // 98
#define LDI 136   // smem A-tile stride in halves (64 rows)
#define LDW 136   // smem W-tile stride in halves (128 rows)

// -------- device scratch (static, allocation-free) --------
__device__ __align__(16) __half g_hA[NN * HH];
__device__ __align__(16) __half g_hB[NN * HH];
__device__ __align__(16) __half g_Wt[3 * HH * HH];   // fp16, transposed [n][k]
__device__ __align__(16) float  g_xa[NN * 4];
__device__ int   g_cnt[NN];
__device__ int   g_fill[NN];
__device__ int   g_rowptr[NN + 1];
__device__ int   g_col[EE];
__device__ float g_dinv[NN];
__device__ int   g_part[NBLK];
__device__ __align__(16) float g_pooled[GG * HH];
__device__ float g_gcnt[GG];
__device__ int   g_shift;   // 0: int32 indices, 1: int64 (read low word)

__device__ __forceinline__ __half* hsel(int k) { return k ? g_hB : g_hA; }

// -------- tensor-core helpers --------
__device__ __forceinline__ void ldsm_x4(unsigned &r0, unsigned &r1, unsigned &r2, unsigned &r3,
                                        unsigned addr) {
    asm volatile("ldmatrix.sync.aligned.m8n8.x4.shared.b16 {%0,%1,%2,%3},[%4];"
                 : "=r"(r0), "=r"(r1), "=r"(r2), "=r"(r3) : "r"(addr));
}
__device__ __forceinline__ void ldsm_x2(unsigned &r0, unsigned &r1, unsigned addr) {
    asm volatile("ldmatrix.sync.aligned.m8n8.x2.shared.b16 {%0,%1},[%2];"
                 : "=r"(r0), "=r"(r1) : "r"(addr));
}
__device__ __forceinline__ void mma16816(float* c, unsigned a0, unsigned a1, unsigned a2,
                                         unsigned a3, unsigned b0, unsigned b1) {
    asm volatile("mma.sync.aligned.m16n8k16.row.col.f32.f16.f16.f32 "
                 "{%0,%1,%2,%3},{%4,%5,%6,%7},{%8,%9},{%0,%1,%2,%3};"
                 : "+f"(c[0]), "+f"(c[1]), "+f"(c[2]), "+f"(c[3])
                 : "r"(a0), "r"(a1), "r"(a2), "r"(a3), "r"(b0), "r"(b1));
}

// -------- dtype detection: sample odd 32-bit words of edge_index --------
__global__ void detect_k(const int* __restrict__ w) {
    __shared__ int sor[256];
    int t = threadIdx.x;
    int o = 0;
    #pragma unroll
    for (int k = 0; k < 16; k++) {
        int j = (t * 16 + k) * (EE / 4096);
        o |= w[2 * j + 1];
    }
    sor[t] = o;
    __syncthreads();
    for (int s = 128; s; s >>= 1) { if (t < s) sor[t] |= sor[t + s]; __syncthreads(); }
    if (t == 0) g_shift = (sor[0] == 0) ? 1 : 0;
}

// -------- zero scratch --------
__global__ void zero_k() {
    int i = blockIdx.x * blockDim.x + threadIdx.x;
    if (i < NN) { g_cnt[i] = 0; g_fill[i] = 0; }
    if (i < GG * HH) g_pooled[i] = 0.0f;
    if (i < GG) g_gcnt[i] = 0.0f;
}

// -------- weight convert: W[k][n] fp32 -> Wt[n][k] fp16, 3 layers --------
__global__ void wcvt_k(const float* __restrict__ W2, const float* __restrict__ W3,
                       const float* __restrict__ W4) {
    int idx = blockIdx.x * blockDim.x + threadIdx.x;
    if (idx >= 3 * HH * HH) return;
    int sel = idx >> 14;           // 16384 per layer
    int loc = idx & 16383;
    int n = loc >> 7, k = loc & 127;
    const float* s = (sel == 0) ? W2 : (sel == 1) ? W3 : W4;
    g_Wt[idx] = __float2half(s[k * HH + n]);
}

// -------- degree count --------
__global__ void count_k(const int* __restrict__ w) {
    int e = blockIdx.x * blockDim.x + threadIdx.x;
    if (e >= EE) return;
    int sh = g_shift;
    int dst = w[(EE + e) << sh];
    atomicAdd(&g_cnt[dst], 1);
}

// -------- scan phase 1: per-block partials --------
__global__ void part_k() {
    __shared__ int red[256];
    int b = blockIdx.x, t = threadIdx.x;
    int base = b * SCAN_CHUNK;
    int v = 0;
    for (int i = t; i < SCAN_CHUNK; i += 256) {
        int idx = base + i;
        if (idx < NN) v += g_cnt[idx];
    }
    red[t] = v;
    __syncthreads();
    for (int s = 128; s; s >>= 1) { if (t < s) red[t] += red[t + s]; __syncthreads(); }
    if (t == 0) g_part[b] = red[0];
}

// -------- scan phase 2: scan partials --------
__global__ void scanpart_k() {
    __shared__ int sp[128];
    int t = threadIdx.x;
    int v = (t < NBLK) ? g_part[t] : 0;
    sp[t] = v;
    __syncthreads();
    for (int off = 1; off < 128; off <<= 1) {
        int u = (t >= off) ? sp[t - off] : 0;
        __syncthreads();
        sp[t] += u;
        __syncthreads();
    }
    if (t < NBLK) g_part[t] = sp[t] - v;
    if (t == 127) g_rowptr[NN] = sp[127];
}

// -------- scan phase 3: rowptr + dinv --------
__global__ void scan3_k() {
    __shared__ int sp[SCAN_CHUNK];
    int b = blockIdx.x, t = threadIdx.x;
    int idx = b * SCAN_CHUNK + t;
    int v = (idx < NN) ? g_cnt[idx] : 0;
    sp[t] = v;
    __syncthreads();
    for (int off = 1; off < SCAN_CHUNK; off <<= 1) {
        int u = (t >= off) ? sp[t - off] : 0;
        __syncthreads();
        sp[t] += u;
        __syncthreads();
    }
    if (idx < NN) {
        g_rowptr[idx] = g_part[b] + sp[t] - v;
        g_dinv[idx] = rsqrtf((float)v + 1.0f);
    }
}

// -------- CSR fill --------
__global__ void fill_k(const int* __restrict__ w) {
    int e = blockIdx.x * blockDim.x + threadIdx.x;
    if (e >= EE) return;
    int sh = g_shift;
    int src = w[e << sh];
    int dst = w[(EE + e) << sh];
    int pos = g_rowptr[dst] + atomicAdd(&g_fill[dst], 1);
    g_col[pos] = src;
}

// -------- aggregate raw x (F=4): warp per node --------
__global__ void aggx_k(const float* __restrict__ x) {
    int warp = (blockIdx.x * blockDim.x + threadIdx.x) >> 5;
    if (warp >= NN) return;
    int lane = threadIdx.x & 31;
    int s = g_rowptr[warp], e = g_rowptr[warp + 1];
    float4 acc = make_float4(0.f, 0.f, 0.f, 0.f);
    const float4* xv = (const float4*)x;
    for (int p = s + lane; p < e; p += 32) {
        int src = g_col[p];
        float w = g_dinv[src];
        float4 v = xv[src];
        acc.x += w * v.x; acc.y += w * v.y; acc.z += w * v.z; acc.w += w * v.w;
    }
    #pragma unroll
    for (int off = 16; off; off >>= 1) {
        acc.x += __shfl_down_sync(0xffffffffu, acc.x, off);
        acc.y += __shfl_down_sync(0xffffffffu, acc.y, off);
        acc.z += __shfl_down_sync(0xffffffffu, acc.z, off);
        acc.w += __shfl_down_sync(0xffffffffu, acc.w, off);
    }
    if (lane == 0) {
        float di = g_dinv[warp];
        float4 sv = xv[warp];
        float wi = di * di;
        float4 o;
        o.x = acc.x * di + sv.x * wi;
        o.y = acc.y * di + sv.y * wi;
        o.z = acc.z * di + sv.z * wi;
        o.w = acc.w * di + sv.w * wi;
        ((float4*)g_xa)[warp] = o;
    }
}

// -------- layer-1 GEMM: xa[N,4]@W1 + b1, relu, prescale -> g_hA fp16 --------
__global__ void gemm1_k(const float* __restrict__ W1, const float* __restrict__ b1) {
    int idx = blockIdx.x * blockDim.x + threadIdx.x;   // NN*64
    if (idx >= NN * 64) return;
    int node = idx >> 6, jc = idx & 63;
    int j = jc * 2;
    float4 a = ((const float4*)g_xa)[node];
    float acc0 = b1[j]     + a.x * W1[j]     + a.y * W1[128 + j]     + a.z * W1[256 + j]     + a.w * W1[384 + j];
    float acc1 = b1[j + 1] + a.x * W1[j + 1] + a.y * W1[128 + j + 1] + a.z * W1[256 + j + 1] + a.w * W1[384 + j + 1];
    float d = g_dinv[node];
    __half2 h = __floats2half2_rn(fmaxf(acc0, 0.f) * d, fmaxf(acc1, 0.f) * d);
    ((__half2*)g_hA)[node * 64 + jc] = h;
}

// -------- fused GCN layer: gather fp16 -> smem A-tile, HMMA GEMM -> fp16 out ----
// 64 nodes/block, 256 threads (8 warps). Dynamic smem: Is[64][136] + Wsm[128][136] fp16.
__global__ __launch_bounds__(256) void layer_k(
    int insel, int wsel, const float* __restrict__ b, int outsel, int prescale) {
    extern __shared__ char dsm[];
    __half* Is  = (__half*)dsm;                 // 64*136*2 = 17408 B
    __half* Wsm = (__half*)(dsm + 64 * LDI * 2); // 128*136*2 = 34816 B
    int t = threadIdx.x, lane = t & 31, wrp = t >> 5;
    int nodeBase = blockIdx.x * 64;
    const uint2* h2 = (const uint2*)hsel(insel);

    // ---- stage Wt tile into smem (padded) ----
    const uint4* Wg = (const uint4*)(g_Wt + wsel * HH * HH);  // 16B = 8 halves
    for (int i = t; i < HH * 16; i += 256) {
        int row = i >> 4, c8 = i & 15;
        *(uint4*)(Wsm + row * LDW + c8 * 8) = Wg[i];
    }

    // ---- gather phase: warp per node (8 nodes/warp), fp16 rows prescaled ----
    #pragma unroll 1
    for (int r = 0; r < 8; r++) {
        int row = wrp * 8 + r;
        int n = nodeBase + row;
        if (n < NN) {
            int s = g_rowptr[n], e = g_rowptr[n + 1];
            uint2 sv = h2[n * 32 + lane];
            float2 lo = __half22float2(*(const __half2*)&sv.x);
            float2 hi = __half22float2(*(const __half2*)&sv.y);
            float4 acc = make_float4(lo.x, lo.y, hi.x, hi.y);
            for (int p = s; p < e; p++) {
                int src = __ldg(&g_col[p]);
                uint2 v = h2[src * 32 + lane];
                float2 l2 = __half22float2(*(const __half2*)&v.x);
                float2 h2f = __half22float2(*(const __half2*)&v.y);
                acc.x += l2.x; acc.y += l2.y; acc.z += h2f.x; acc.w += h2f.y;
            }
            float d = g_dinv[n];
            __half2 p0 = __floats2half2_rn(acc.x * d, acc.y * d);
            __half2 p1 = __floats2half2_rn(acc.z * d, acc.w * d);
            uint2 st;
            st.x = *(unsigned*)&p0;
            st.y = *(unsigned*)&p1;
            ((uint2*)(Is + row * LDI))[lane] = st;
        } else {
            ((uint2*)(Is + row * LDI))[lane] = make_uint2(0u, 0u);
        }
    }
    __syncthreads();

    // ---- GEMM phase: Is[64,128] @ Wt^T via mma.m16n8k16 ----
    int mtile = wrp & 3;     // 4 M-tiles of 16
    int nhalf = wrp >> 2;    // 2 N-halves of 64
    unsigned a_base = (unsigned)__cvta_generic_to_shared(
        Is + (mtile * 16 + (lane & 15)) * LDI + (lane >> 4) * 8);
    unsigned b_base = (unsigned)__cvta_generic_to_shared(
        Wsm + (nhalf * 64 + (lane & 7)) * LDW + ((lane >> 3) & 1) * 8);

    float acc[8][4];
    #pragma unroll
    for (int i = 0; i < 8; i++)
        #pragma unroll
        for (int j = 0; j < 4; j++) acc[i][j] = 0.f;

    #pragma unroll
    for (int k = 0; k < 8; k++) {
        unsigned a0, a1, a2, a3;
        ldsm_x4(a0, a1, a2, a3, a_base + k * 32);
        #pragma unroll
        for (int n8 = 0; n8 < 8; n8++) {
            unsigned b0, b1;
            ldsm_x2(b0, b1, b_base + n8 * 8 * LDW * 2 + k * 32);
            mma16816(acc[n8], a0, a1, a2, a3, b0, b1);
        }
    }

    // ---- epilogue: bias, relu, prescale, fp16 store ----
    int mr = lane >> 2;
    int nc = (lane & 3) * 2;
    int node0 = nodeBase + mtile * 16 + mr;
    int node1 = node0 + 8;
    bool v0 = node0 < NN, v1 = node1 < NN;
    float d0 = 1.f, d1 = 1.f;
    if (prescale) {
        if (v0) d0 = g_dinv[node0];
        if (v1) d1 = g_dinv[node1];
    }
    __half* hout = hsel(outsel);
    #pragma unroll
    for (int n8 = 0; n8 < 8; n8++) {
        int n = nhalf * 64 + n8 * 8 + nc;
        float2 bb = *(const float2*)&b[n];
        if (v0) {
            __half2 p = __floats2half2_rn(fmaxf(acc[n8][0] + bb.x, 0.f) * d0,
                                          fmaxf(acc[n8][1] + bb.y, 0.f) * d0);
            *(__half2*)(hout + node0 * HH + n) = p;
        }
        if (v1) {
            __half2 p = __floats2half2_rn(fmaxf(acc[n8][2] + bb.x, 0.f) * d1,
                                          fmaxf(acc[n8][3] + bb.y, 0.f) * d1);
            *(__half2*)(hout + node1 * HH + n) = p;
        }
    }
}

// -------- global mean pool: segment-accumulate (batch is sorted) --------
__global__ void pool_k(const int* __restrict__ wbatch, int insel) {
    int warp = (blockIdx.x * blockDim.x + threadIdx.x) >> 5;
    int lane = threadIdx.x & 31;
    int base = warp * 16;
    if (base >= NN) return;
    int sh = g_shift;
    const uint2* hv = (const uint2*)hsel(insel);
    int end = base + 16; if (end > NN) end = NN;
    float4 acc = make_float4(0.f, 0.f, 0.f, 0.f);
    int cur = wbatch[base << sh];
    int cnt = 0;
    for (int n = base; n < end; n++) {
        int g = wbatch[n << sh];
        if (g != cur) {
            float* bp = &g_pooled[cur * HH + lane * 4];
            atomicAdd(bp + 0, acc.x); atomicAdd(bp + 1, acc.y);
            atomicAdd(bp + 2, acc.z); atomicAdd(bp + 3, acc.w);
            if (lane == 0) atomicAdd(&g_gcnt[cur], (float)cnt);
            acc = make_float4(0.f, 0.f, 0.f, 0.f);
            cnt = 0; cur = g;
        }
        uint2 v = hv[n * 32 + lane];
        float2 lo = __half22float2(*(const __half2*)&v.x);
        float2 hi = __half22float2(*(const __half2*)&v.y);
        acc.x += lo.x; acc.y += lo.y; acc.z += hi.x; acc.w += hi.y;
        cnt++;
    }
    float* bp = &g_pooled[cur * HH + lane * 4];
    atomicAdd(bp + 0, acc.x); atomicAdd(bp + 1, acc.y);
    atomicAdd(bp + 2, acc.z); atomicAdd(bp + 3, acc.w);
    if (lane == 0) atomicAdd(&g_gcnt[cur], (float)cnt);
}

// -------- classifier head --------
__global__ void final_k(const float* __restrict__ Wl, const float* __restrict__ bl,
                        float* __restrict__ out) {
    int idx = blockIdx.x * blockDim.x + threadIdx.x;
    if (idx >= GG * CC) return;
    int g = idx / CC, c = idx % CC;
    float inv = 1.0f / fmaxf(g_gcnt[g], 1.0f);
    float acc = bl[c];
    const float* pr = &g_pooled[g * HH];
    #pragma unroll 4
    for (int k = 0; k < HH; k++) acc += pr[k] * inv * Wl[k * CC + c];
    out[idx] = 1.0f / (1.0f + expf(-acc));
}

extern "C" void kernel_launch(void* const* d_in, const int* in_sizes, int n_in,
                              void* d_out, int out_size) {
    const float* x    = (const float*)d_in[0];
    const int*   eiw  = (const int*)d_in[1];
    const int*   batw = (const int*)d_in[2];
    const float* W1 = (const float*)d_in[3];
    const float* b1 = (const float*)d_in[4];
    const float* W2 = (const float*)d_in[5];
    const float* b2 = (const float*)d_in[6];
    const float* W3 = (const float*)d_in[7];
    const float* b3 = (const float*)d_in[8];
    const float* W4 = (const float*)d_in[9];
    const float* b4 = (const float*)d_in[10];
    const float* Wl = (const float*)d_in[11];
    const float* bl = (const float*)d_in[12];
    float* out = (float*)d_out;

    const int LAYER_SMEM = (64 * LDI + HH * LDW) * 2;   // 52224 B
    static int attr_done = 0;
    if (!attr_done) {
        cudaFuncSetAttribute(layer_k, cudaFuncAttributeMaxDynamicSharedMemorySize, LAYER_SMEM);
        attr_done = 1;
    }

    // ---- dtype detect + weight convert + CSR build ----
    detect_k<<<1, 256>>>(eiw);
    zero_k<<<(NN + 255) / 256, 256>>>();
    wcvt_k<<<(3 * HH * HH + 255) / 256, 256>>>(W2, W3, W4);
    count_k<<<(EE + 255) / 256, 256>>>(eiw);
    part_k<<<NBLK, 256>>>();
    scanpart_k<<<1, 128>>>();
    scan3_k<<<NBLK, SCAN_CHUNK>>>();
    fill_k<<<(EE + 255) / 256, 256>>>(eiw);

    const int WARP_BLOCKS = (NN * 32 + 255) / 256;
    const int LAYER_BLOCKS = (NN + 63) / 64;

    // ---- layer 1: aggregate x (F=4), GEMM W1 -> g_hA (prescaled fp16) ----
    aggx_k<<<WARP_BLOCKS, 256>>>(x);
    gemm1_k<<<(NN * 64 + 255) / 256, 256>>>(W1, b1);

    // ---- layers 2-4: fused gather + tensor-core GEMM (ping-pong A<->B) ----
    layer_k<<<LAYER_BLOCKS, 256, LAYER_SMEM>>>(0, 0, b2, 1, 1);
    layer_k<<<LAYER_BLOCKS, 256, LAYER_SMEM>>>(1, 1, b3, 0, 1);
    layer_k<<<LAYER_BLOCKS, 256, LAYER_SMEM>>>(0, 2, b4, 1, 0);   // last: no prescale

    // ---- global mean pool + head ----
    const int POOL_BLOCKS = ((NN + 15) / 16 * 32 + 255) / 256;
    pool_k<<<POOL_BLOCKS, 256>>>(batw, 1);
    final_k<<<(GG * CC + 255) / 256, 256>>>(Wl, bl, out);
}